// round 11
// baseline (speedup 1.0000x reference)
#include <cuda_runtime.h>
#include <cuda_bf16.h>
#include <math.h>

#define HDIM 128
#define MAXN 100608
#define MAXE 1700000
#define NGRAPH 64

// ---------------- device scratch (no allocation allowed) ----------------
__device__ float  g_deg[MAXN];                  // dinv = 1/sqrt(deg)
__device__ int    g_degi[MAXN];                 // in-degree (without self loop)
__device__ int    g_off[MAXN];                  // CSR offsets (exclusive scan)
__device__ int    g_cursor[MAXN];               // scatter cursors
__device__ int    g_blocksum[128];              // scan partials
__device__ int2   g_csr[MAXE];                  // {src, dinv[src] as bits}
__device__ float4 g_x4[MAXN];                   // packed input features [a,px,py,pz]
__device__ float4 g_x4agg[MAXN];                // aggregated input features
__device__ float  g_buf0[(size_t)MAXN * HDIM];  // X / AGG buffer
__device__ float  g_buf1[(size_t)MAXN * HDIM];  // H (transformed) buffer
__device__ float  g_pool[NGRAPH * HDIM];
__device__ float  g_cnt[NGRAPH];
__device__ int    g_edge_is64;
__device__ int    g_batch_is64;

// ---------------- packed f32x2 helpers (sm_103a FFMA2, PTX-only) --------
__device__ __forceinline__ void ffma2(unsigned long long& acc,
                                      unsigned long long a,
                                      unsigned long long b) {
    asm("fma.rn.f32x2 %0, %1, %2, %0;" : "+l"(acc) : "l"(a), "l"(b));
}
__device__ __forceinline__ unsigned long long pack2(float lo, float hi) {
    unsigned long long r;
    asm("mov.b64 %0, {%1, %2};" : "=l"(r) : "f"(lo), "f"(hi));
    return r;
}
__device__ __forceinline__ void unpack2(unsigned long long v, float& lo, float& hi) {
    asm("mov.b64 {%0, %1}, %2;" : "=f"(lo), "=f"(hi) : "l"(v));
}

// ---------------- streaming (evict-first) access helpers ----------------
__device__ __forceinline__ int2 ldcs_int2(const int2* p) {
    int2 r;
    asm("ld.global.cs.v2.s32 {%0, %1}, [%2];" : "=r"(r.x), "=r"(r.y) : "l"(p));
    return r;
}
__device__ __forceinline__ float4 ldcs_float4(const float4* p) {
    float4 r;
    asm("ld.global.cs.v4.f32 {%0, %1, %2, %3}, [%4];"
        : "=f"(r.x), "=f"(r.y), "=f"(r.z), "=f"(r.w) : "l"(p));
    return r;
}
__device__ __forceinline__ void stcs_float2(float2* p, float2 v) {
    asm("st.global.cs.v2.f32 [%0], {%1, %2};"
        :: "l"(p), "f"(v.x), "f"(v.y) : "memory");
}
__device__ __forceinline__ float ldcs_float(const float* p) {
    float r;
    asm("ld.global.cs.f32 %0, [%1];" : "=f"(r) : "l"(p));
    return r;
}
__device__ __forceinline__ void stcs_float(float* p, float v) {
    asm("st.global.cs.f32 [%0], %1;" :: "l"(p), "f"(v) : "memory");
}

// ---------------- index helper: int64 vs int32 storage ----------------
__device__ __forceinline__ long long ld_idx(const void* p, long long i, int is64) {
    if (is64) return ((const long long*)p)[i];
    return (long long)((const int*)p)[i];
}

// ---------------- detect dtypes + zero degree arrays (merged) ----------
__global__ void detect_zero_kernel(const void* edge, const void* batch, int N) {
    int i = blockIdx.x * blockDim.x + threadIdx.x;
    if (i < N) { g_degi[i] = 0; g_cursor[i] = 0; }
    if (blockIdx.x == 0 && threadIdx.x < 64) {
        int lane = threadIdx.x & 31;
        int w    = threadIdx.x >> 5;
        const long long* p = (w == 0) ? (const long long*)edge
                                      : (const long long*)batch;
        long long v0 = p[lane * 2];
        long long v1 = p[lane * 2 + 1];
        int bad = (v0 < 0) | (v0 >= (1LL << 31)) | (v1 < 0) | (v1 >= (1LL << 31));
        unsigned m = __ballot_sync(0xFFFFFFFFu, bad);
        if (lane == 0) {
            int ok = (m == 0u);
            if (w == 0) g_edge_is64 = ok; else g_batch_is64 = ok;
        }
    }
}

__global__ void count_deg_kernel(const void* edge, int E) {
    int e = blockIdx.x * blockDim.x + threadIdx.x;
    if (e >= E) return;
    int is64 = g_edge_is64;
    int d = (int)ld_idx(edge, (long long)E + e, is64);
    atomicAdd(&g_degi[d], 1);
}

// also packs x4 = [a, pos] (fused; same launch shape)
__global__ void dinv_kernel(const float* __restrict__ an,
                            const float* __restrict__ pos, int N) {
    int i = blockIdx.x * blockDim.x + threadIdx.x;
    if (i >= N) return;
    g_deg[i] = (float)(1.0 / sqrt((double)(g_degi[i] + 1)));
    float4 x;
    x.x = an[i];
    x.y = pos[3 * i + 0];
    x.z = pos[3 * i + 1];
    x.w = pos[3 * i + 2];
    g_x4[i] = x;
}

// ---------------- exclusive prefix scan of g_degi -> g_off ----------------
__global__ void __launch_bounds__(256) scan1_kernel(int N) {
    __shared__ int sh[256];
    int t = threadIdx.x;
    int base = blockIdx.x * 1024 + t * 4;
    int v0 = (base + 0 < N) ? g_degi[base + 0] : 0;
    int v1 = (base + 1 < N) ? g_degi[base + 1] : 0;
    int v2 = (base + 2 < N) ? g_degi[base + 2] : 0;
    int v3 = (base + 3 < N) ? g_degi[base + 3] : 0;
    int sum = v0 + v1 + v2 + v3;
    sh[t] = sum;
    __syncthreads();
    for (int o = 1; o < 256; o <<= 1) {
        int x = (t >= o) ? sh[t - o] : 0;
        __syncthreads();
        sh[t] += x;
        __syncthreads();
    }
    if (t == 255) g_blocksum[blockIdx.x] = sh[255];
    int run = sh[t] - sum;
    if (base + 0 < N) { g_off[base + 0] = run; run += v0; }
    if (base + 1 < N) { g_off[base + 1] = run; run += v1; }
    if (base + 2 < N) { g_off[base + 2] = run; run += v2; }
    if (base + 3 < N) { g_off[base + 3] = run; }
}

__global__ void scan2_kernel(int nb) {
    __shared__ int sh[128];
    int t = threadIdx.x;
    int v = (t < nb) ? g_blocksum[t] : 0;
    sh[t] = v;
    __syncthreads();
    for (int o = 1; o < 128; o <<= 1) {
        int x = (t >= o) ? sh[t - o] : 0;
        __syncthreads();
        sh[t] += x;
        __syncthreads();
    }
    g_blocksum[t] = sh[t] - v;
}

__global__ void scan3_kernel(int N) {
    int i = blockIdx.x * blockDim.x + threadIdx.x;
    if (i < N) g_off[i] += g_blocksum[i >> 10];
}

// ---------------- CSR scatter ----------------
__global__ void scatter_kernel(const void* edge, int E) {
    int e = blockIdx.x * blockDim.x + threadIdx.x;
    if (e >= E) return;
    int is64 = g_edge_is64;
    int s = (int)ld_idx(edge, e, is64);
    int d = (int)ld_idx(edge, (long long)E + e, is64);
    int pos = atomicAdd(&g_cursor[d], 1);
    int2 ent;
    ent.x = s;
    ent.y = __float_as_int(g_deg[s]);
    g_csr[g_off[d] + pos] = ent;
}

// ---------------- layer-1 aggregation on RAW 4-dim features ------------
__global__ void __launch_bounds__(256) agg4_kernel(int N) {
    int d = blockIdx.x * blockDim.x + threadIdx.x;
    if (d >= N) return;
    int off = g_off[d];
    int deg = g_degi[d];
    float dn = g_deg[d];

    float4 x = g_x4[d];
    float4 acc;
    acc.x = x.x * dn; acc.y = x.y * dn; acc.z = x.z * dn; acc.w = x.w * dn;

    int end = off + deg;
    int e0 = off;
    for (; e0 + 4 <= end; e0 += 4) {
        int2 en0 = ldcs_int2(&g_csr[e0 + 0]);
        int2 en1 = ldcs_int2(&g_csr[e0 + 1]);
        int2 en2 = ldcs_int2(&g_csr[e0 + 2]);
        int2 en3 = ldcs_int2(&g_csr[e0 + 3]);
        float4 v0 = g_x4[en0.x];
        float4 v1 = g_x4[en1.x];
        float4 v2 = g_x4[en2.x];
        float4 v3 = g_x4[en3.x];
        float w0 = __int_as_float(en0.y), w1 = __int_as_float(en1.y);
        float w2 = __int_as_float(en2.y), w3 = __int_as_float(en3.y);
        acc.x += w0 * v0.x; acc.y += w0 * v0.y; acc.z += w0 * v0.z; acc.w += w0 * v0.w;
        acc.x += w1 * v1.x; acc.y += w1 * v1.y; acc.z += w1 * v1.z; acc.w += w1 * v1.w;
        acc.x += w2 * v2.x; acc.y += w2 * v2.y; acc.z += w2 * v2.z; acc.w += w2 * v2.w;
        acc.x += w3 * v3.x; acc.y += w3 * v3.y; acc.z += w3 * v3.z; acc.w += w3 * v3.w;
    }
    for (; e0 < end; e0++) {
        int2 en = ldcs_int2(&g_csr[e0]);
        float4 v = g_x4[en.x];
        float w = __int_as_float(en.y);
        acc.x += w * v.x; acc.y += w * v.y; acc.z += w * v.z; acc.w += w * v.w;
    }
    acc.x *= dn; acc.y *= dn; acc.z *= dn; acc.w *= dn;
    g_x4agg[d] = acc;
}

// ---------------- layer-1 transform: (N,4)@(4,128) + bias + relu -------
__global__ void transform1_kernel(const float* __restrict__ W0,
                                  const float* __restrict__ b0, int N) {
    int idx = blockIdx.x * blockDim.x + threadIdx.x;
    if (idx >= N * HDIM) return;
    int n = idx >> 7, j = idx & 127;
    float4 x = g_x4agg[n];
    float h = x.x * W0[j] + x.y * W0[HDIM + j] + x.z * W0[2 * HDIM + j]
            + x.w * W0[3 * HDIM + j] + b0[j];
    stcs_float(&g_buf0[idx], h > 0.0f ? h : 0.0f);
}

// ---------------- column-split aggregation + self-loop + bias + relu ---
// Processes only 64 of the 128 columns per launch (half = 0 or 1), so
// the randomly-gathered hot set is 25.5MB (fits L2 with room to spare)
// instead of 51MB (thrash). One warp per dst node; lane l owns float2 at
// column half*64 + 2l. Edge accumulation order per output element is
// IDENTICAL to the full-width version -> bit-identical results.
__global__ void __launch_bounds__(256) agg_half_kernel(const float* __restrict__ bias,
                                                       int N, int half) {
    int warp = (blockIdx.x * 256 + threadIdx.x) >> 5;
    int lane = threadIdx.x & 31;
    if (warp >= N) return;
    int d   = warp;
    int off = g_off[d];
    int deg = g_degi[d];
    float dn = g_deg[d];
    int colbase = half * 64;            // float offset within row

    const float2* selfp = (const float2*)&g_buf1[(size_t)d * HDIM + colbase];
    float2 h = selfp[lane];
    float2 acc;
    acc.x = h.x * dn; acc.y = h.y * dn;

    int end = off + deg;
    int e0 = off;
    for (; e0 + 8 <= end; e0 += 8) {
        int2 en0 = ldcs_int2(&g_csr[e0 + 0]);
        int2 en1 = ldcs_int2(&g_csr[e0 + 1]);
        int2 en2 = ldcs_int2(&g_csr[e0 + 2]);
        int2 en3 = ldcs_int2(&g_csr[e0 + 3]);
        int2 en4 = ldcs_int2(&g_csr[e0 + 4]);
        int2 en5 = ldcs_int2(&g_csr[e0 + 5]);
        int2 en6 = ldcs_int2(&g_csr[e0 + 6]);
        int2 en7 = ldcs_int2(&g_csr[e0 + 7]);
        float2 v0 = ((const float2*)&g_buf1[(size_t)en0.x * HDIM + colbase])[lane];
        float2 v1 = ((const float2*)&g_buf1[(size_t)en1.x * HDIM + colbase])[lane];
        float2 v2 = ((const float2*)&g_buf1[(size_t)en2.x * HDIM + colbase])[lane];
        float2 v3 = ((const float2*)&g_buf1[(size_t)en3.x * HDIM + colbase])[lane];
        float2 v4 = ((const float2*)&g_buf1[(size_t)en4.x * HDIM + colbase])[lane];
        float2 v5 = ((const float2*)&g_buf1[(size_t)en5.x * HDIM + colbase])[lane];
        float2 v6 = ((const float2*)&g_buf1[(size_t)en6.x * HDIM + colbase])[lane];
        float2 v7 = ((const float2*)&g_buf1[(size_t)en7.x * HDIM + colbase])[lane];
        float w0 = __int_as_float(en0.y), w1 = __int_as_float(en1.y);
        float w2 = __int_as_float(en2.y), w3 = __int_as_float(en3.y);
        float w4 = __int_as_float(en4.y), w5 = __int_as_float(en5.y);
        float w6 = __int_as_float(en6.y), w7 = __int_as_float(en7.y);
        acc.x += w0 * v0.x; acc.y += w0 * v0.y;
        acc.x += w1 * v1.x; acc.y += w1 * v1.y;
        acc.x += w2 * v2.x; acc.y += w2 * v2.y;
        acc.x += w3 * v3.x; acc.y += w3 * v3.y;
        acc.x += w4 * v4.x; acc.y += w4 * v4.y;
        acc.x += w5 * v5.x; acc.y += w5 * v5.y;
        acc.x += w6 * v6.x; acc.y += w6 * v6.y;
        acc.x += w7 * v7.x; acc.y += w7 * v7.y;
    }
    for (; e0 + 4 <= end; e0 += 4) {
        int2 en0 = ldcs_int2(&g_csr[e0 + 0]);
        int2 en1 = ldcs_int2(&g_csr[e0 + 1]);
        int2 en2 = ldcs_int2(&g_csr[e0 + 2]);
        int2 en3 = ldcs_int2(&g_csr[e0 + 3]);
        float2 v0 = ((const float2*)&g_buf1[(size_t)en0.x * HDIM + colbase])[lane];
        float2 v1 = ((const float2*)&g_buf1[(size_t)en1.x * HDIM + colbase])[lane];
        float2 v2 = ((const float2*)&g_buf1[(size_t)en2.x * HDIM + colbase])[lane];
        float2 v3 = ((const float2*)&g_buf1[(size_t)en3.x * HDIM + colbase])[lane];
        float w0 = __int_as_float(en0.y), w1 = __int_as_float(en1.y);
        float w2 = __int_as_float(en2.y), w3 = __int_as_float(en3.y);
        acc.x += w0 * v0.x; acc.y += w0 * v0.y;
        acc.x += w1 * v1.x; acc.y += w1 * v1.y;
        acc.x += w2 * v2.x; acc.y += w2 * v2.y;
        acc.x += w3 * v3.x; acc.y += w3 * v3.y;
    }
    for (; e0 < end; e0++) {
        int2 en = ldcs_int2(&g_csr[e0]);
        float2 v = ((const float2*)&g_buf1[(size_t)en.x * HDIM + colbase])[lane];
        float w = __int_as_float(en.y);
        acc.x += w * v.x; acc.y += w * v.y;
    }

    float2 b = ((const float2*)(bias + colbase))[lane];
    float2 r;
    r.x = fmaxf(acc.x * dn + b.x, 0.0f);
    r.y = fmaxf(acc.y * dn + b.y, 0.0f);
    stcs_float2(&((float2*)&g_buf0[(size_t)d * HDIM + colbase])[lane], r);
}

// ---------------- layers 2/3: register-tiled FFMA2 GEMM (R10 winner) ---
#define NPB 32
__global__ void __launch_bounds__(128) gemm_kernel(const float* __restrict__ W, int N) {
    __shared__ float4 Xs[NPB][HDIM / 4];   // 16 KB
    int n0  = blockIdx.x * NPB;
    int tid = threadIdx.x;
    int c   = tid & 31;        // cols 4c .. 4c+3
    int rg  = tid >> 5;        // rows rg*8 .. rg*8+7

    #pragma unroll
    for (int i = 0; i < 8; i++) {
        int idx = i * 128 + tid;
        int r = idx >> 5, cc = idx & 31;
        int n = n0 + r;
        Xs[r][cc] = (n < N) ? ldcs_float4(&((const float4*)&g_buf0[(size_t)n * HDIM])[cc])
                            : make_float4(0.f, 0.f, 0.f, 0.f);
    }
    __syncthreads();

    unsigned long long acc[8][2];
    #pragma unroll
    for (int r = 0; r < 8; r++) { acc[r][0] = 0ULL; acc[r][1] = 0ULL; }

    for (int k4 = 0; k4 < HDIM / 4; k4++) {
        unsigned long long w[4][2];
        #pragma unroll
        for (int kk = 0; kk < 4; kk++) {
            ulonglong2 wv = *reinterpret_cast<const ulonglong2*>(
                &W[(k4 * 4 + kk) * HDIM + 4 * c]);
            w[kk][0] = wv.x; w[kk][1] = wv.y;
        }
        #pragma unroll
        for (int r = 0; r < 8; r++) {
            float4 x = Xs[rg * 8 + r][k4];   // broadcast LDS across warp
            unsigned long long xd;
            xd = pack2(x.x, x.x); ffma2(acc[r][0], xd, w[0][0]); ffma2(acc[r][1], xd, w[0][1]);
            xd = pack2(x.y, x.y); ffma2(acc[r][0], xd, w[1][0]); ffma2(acc[r][1], xd, w[1][1]);
            xd = pack2(x.z, x.z); ffma2(acc[r][0], xd, w[2][0]); ffma2(acc[r][1], xd, w[2][1]);
            xd = pack2(x.w, x.w); ffma2(acc[r][0], xd, w[3][0]); ffma2(acc[r][1], xd, w[3][1]);
        }
    }

    #pragma unroll
    for (int r = 0; r < 8; r++) {
        int n = n0 + rg * 8 + r;
        if (n < N) {
            float4 o;
            unpack2(acc[r][0], o.x, o.y);
            unpack2(acc[r][1], o.z, o.w);
            *reinterpret_cast<float4*>(&g_buf1[(size_t)n * HDIM + 4 * c]) = o;
        }
    }
}

// ---------------- pooling ----------------
__global__ void pool_zero_kernel() {
    int i = blockIdx.x * blockDim.x + threadIdx.x;
    if (i < NGRAPH * HDIM) g_pool[i] = 0.0f;
    if (i < NGRAPH) g_cnt[i] = 0.0f;
}

#define POOL_NODES 512
__global__ void __launch_bounds__(128) pool_acc_kernel(const void* batch, int N) {
    int j  = threadIdx.x;
    int n0 = blockIdx.x * POOL_NODES;
    int n1 = min(n0 + POOL_NODES, N);
    int is64 = g_batch_is64;
    double acc = 0.0;
    float cnt = 0.0f;
    int cur = -1;
    for (int n = n0; n < n1; n++) {
        int g = (int)ld_idx(batch, n, is64);
        if (g != cur) {
            if (cur >= 0) {
                atomicAdd(&g_pool[cur * HDIM + j], (float)acc);
                if (j == 0) atomicAdd(&g_cnt[cur], cnt);
            }
            cur = g; acc = 0.0; cnt = 0.0f;
        }
        acc += (double)ldcs_float(&g_buf0[(size_t)n * HDIM + j]);
        cnt += 1.0f;
    }
    if (cur >= 0) {
        atomicAdd(&g_pool[cur * HDIM + j], (float)acc);
        if (j == 0) atomicAdd(&g_cnt[cur], cnt);
    }
}

// ---------------- head: mean, linear(128->8), softmax (double) ---------
__global__ void final_kernel(const float* __restrict__ linW,
                             const float* __restrict__ linb,
                             float* __restrict__ out) {
    int t = threadIdx.x;             // 512 = 64 graphs * 8 experts
    int g = t >> 3, e = t & 7;
    double c = (double)fmaxf(g_cnt[g], 1.0f);
    double acc = 0.0;
    #pragma unroll 8
    for (int k = 0; k < HDIM; k++)
        acc += (double)g_pool[g * HDIM + k] * (double)linW[k * 8 + e];
    double logit = acc / c + (double)linb[e];
    double m = logit;
    for (int o = 4; o >= 1; o >>= 1) {
        double other = __shfl_xor_sync(0xFFFFFFFFu, m, o);
        m = fmax(m, other);
    }
    double ex = exp(logit - m);
    double s = ex;
    for (int o = 4; o >= 1; o >>= 1)
        s += __shfl_xor_sync(0xFFFFFFFFu, s, o);
    out[t] = (float)(ex / s);
}

// ---------------- launch ----------------
extern "C" void kernel_launch(void* const* d_in, const int* in_sizes, int n_in,
                              void* d_out, int out_size) {
    const float* an   = (const float*)d_in[0];
    const float* pos  = (const float*)d_in[1];
    const float* W0   = (const float*)d_in[2];
    const float* b0   = (const float*)d_in[3];
    const float* W1   = (const float*)d_in[4];
    const float* b1   = (const float*)d_in[5];
    const float* W2   = (const float*)d_in[6];
    const float* b2   = (const float*)d_in[7];
    const float* linW = (const float*)d_in[8];
    const float* linb = (const float*)d_in[9];
    const void*  edge = d_in[10];
    const void*  batch= d_in[11];
    int N = in_sizes[0];
    int E = in_sizes[10] / 2;
    float* out = (float*)d_out;

    // prologue: degrees, norms, features, CSR
    detect_zero_kernel<<<(N + 255) / 256, 256>>>(edge, batch, N);
    count_deg_kernel<<<(E + 255) / 256, 256>>>(edge, E);
    dinv_kernel<<<(N + 255) / 256, 256>>>(an, pos, N);
    int nb = (N + 1023) / 1024;
    scan1_kernel<<<nb, 256>>>(N);
    scan2_kernel<<<1, 128>>>(nb);
    scan3_kernel<<<(N + 255) / 256, 256>>>(N);
    scatter_kernel<<<(E + 255) / 256, 256>>>(edge, E);

    int nh = N * HDIM;
    int agg_grid = (N + 7) / 8;
    // layer 1: aggregate raw 4-dim features, then transform+bias+relu
    agg4_kernel<<<(N + 255) / 256, 256>>>(N);
    transform1_kernel<<<(nh + 255) / 256, 256>>>(W0, b0, N);
    // layer 2
    gemm_kernel<<<(N + NPB - 1) / NPB, 128>>>(W1, N);
    agg_half_kernel<<<agg_grid, 256>>>(b1, N, 0);
    agg_half_kernel<<<agg_grid, 256>>>(b1, N, 1);
    // layer 3
    gemm_kernel<<<(N + NPB - 1) / NPB, 128>>>(W2, N);
    agg_half_kernel<<<agg_grid, 256>>>(b2, N, 0);
    agg_half_kernel<<<agg_grid, 256>>>(b2, N, 1);
    // pool + head
    pool_zero_kernel<<<(NGRAPH * HDIM + 255) / 256, 256>>>();
    pool_acc_kernel<<<(N + POOL_NODES - 1) / POOL_NODES, 128>>>(batch, N);
    final_kernel<<<1, 512>>>(linW, linb, out);
}

// round 13
// speedup vs baseline: 1.1823x; 1.1823x over previous
#include <cuda_runtime.h>
#include <cuda_bf16.h>
#include <cstdint>
#include <math.h>

#define HDIM 128
#define MAXN 100608
#define MAXE 1700000
#define NGRAPH 64

// ---------------- device scratch (no allocation allowed) ----------------
__device__ float  g_deg[MAXN];                  // dinv = 1/sqrt(deg)
__device__ int    g_degi[MAXN];                 // in-degree (without self loop)
__device__ int    g_off[MAXN];                  // CSR offsets (exclusive scan)
__device__ int    g_cursor[MAXN];               // scatter cursors
__device__ int    g_blocksum[128];              // scan partials
__device__ int2   g_csr[MAXE];                  // {src, dinv[src] as bits}
__device__ float4 g_x4[MAXN];                   // packed input features [a,px,py,pz]
__device__ float4 g_x4agg[MAXN];                // aggregated input features
__device__ float  g_buf0[(size_t)MAXN * HDIM];  // X / AGG buffer
__device__ float  g_buf1[(size_t)MAXN * HDIM];  // H (transformed) buffer
__device__ float  g_pool[NGRAPH * HDIM];
__device__ float  g_cnt[NGRAPH];
__device__ int    g_edge_is64;
__device__ int    g_batch_is64;

// ---------------- tf32 helpers -----------------------------------------
__device__ __forceinline__ unsigned int to_tf32(float v) {
    unsigned int t;
    asm("cvt.rna.tf32.f32 %0, %1;" : "=r"(t) : "f"(v));
    return t;
}
__device__ __forceinline__ float to_tf32f(float v) {
    return __uint_as_float(to_tf32(v));
}

// ---------------- streaming (evict-first) access helpers ----------------
__device__ __forceinline__ int2 ldcs_int2(const int2* p) {
    int2 r;
    asm("ld.global.cs.v2.s32 {%0, %1}, [%2];" : "=r"(r.x), "=r"(r.y) : "l"(p));
    return r;
}
__device__ __forceinline__ void stcs_float4(float4* p, float4 v) {
    asm("st.global.cs.v4.f32 [%0], {%1, %2, %3, %4};"
        :: "l"(p), "f"(v.x), "f"(v.y), "f"(v.z), "f"(v.w) : "memory");
}
__device__ __forceinline__ float ldcs_float(const float* p) {
    float r;
    asm("ld.global.cs.f32 %0, [%1];" : "=f"(r) : "l"(p));
    return r;
}
__device__ __forceinline__ void stcs_float(float* p, float v) {
    asm("st.global.cs.f32 [%0], %1;" :: "l"(p), "f"(v) : "memory");
}

// ---------------- index helper: int64 vs int32 storage ----------------
__device__ __forceinline__ long long ld_idx(const void* p, long long i, int is64) {
    if (is64) return ((const long long*)p)[i];
    return (long long)((const int*)p)[i];
}

// ---------------- detect dtypes + zero degree arrays (merged) ----------
__global__ void detect_zero_kernel(const void* edge, const void* batch, int N) {
    int i = blockIdx.x * blockDim.x + threadIdx.x;
    if (i < N) { g_degi[i] = 0; g_cursor[i] = 0; }
    if (blockIdx.x == 0 && threadIdx.x < 64) {
        int lane = threadIdx.x & 31;
        int w    = threadIdx.x >> 5;
        const long long* p = (w == 0) ? (const long long*)edge
                                      : (const long long*)batch;
        long long v0 = p[lane * 2];
        long long v1 = p[lane * 2 + 1];
        int bad = (v0 < 0) | (v0 >= (1LL << 31)) | (v1 < 0) | (v1 >= (1LL << 31));
        unsigned m = __ballot_sync(0xFFFFFFFFu, bad);
        if (lane == 0) {
            int ok = (m == 0u);
            if (w == 0) g_edge_is64 = ok; else g_batch_is64 = ok;
        }
    }
}

__global__ void count_deg_kernel(const void* edge, int E) {
    int e = blockIdx.x * blockDim.x + threadIdx.x;
    if (e >= E) return;
    int is64 = g_edge_is64;
    int d = (int)ld_idx(edge, (long long)E + e, is64);
    atomicAdd(&g_degi[d], 1);
}

// also packs x4 = [a, pos] (fused; same launch shape)
__global__ void dinv_kernel(const float* __restrict__ an,
                            const float* __restrict__ pos, int N) {
    int i = blockIdx.x * blockDim.x + threadIdx.x;
    if (i >= N) return;
    g_deg[i] = (float)(1.0 / sqrt((double)(g_degi[i] + 1)));
    float4 x;
    x.x = an[i];
    x.y = pos[3 * i + 0];
    x.z = pos[3 * i + 1];
    x.w = pos[3 * i + 2];
    g_x4[i] = x;
}

// ---------------- exclusive prefix scan of g_degi -> g_off ----------------
__global__ void __launch_bounds__(256) scan1_kernel(int N) {
    __shared__ int sh[256];
    int t = threadIdx.x;
    int base = blockIdx.x * 1024 + t * 4;
    int v0 = (base + 0 < N) ? g_degi[base + 0] : 0;
    int v1 = (base + 1 < N) ? g_degi[base + 1] : 0;
    int v2 = (base + 2 < N) ? g_degi[base + 2] : 0;
    int v3 = (base + 3 < N) ? g_degi[base + 3] : 0;
    int sum = v0 + v1 + v2 + v3;
    sh[t] = sum;
    __syncthreads();
    for (int o = 1; o < 256; o <<= 1) {
        int x = (t >= o) ? sh[t - o] : 0;
        __syncthreads();
        sh[t] += x;
        __syncthreads();
    }
    if (t == 255) g_blocksum[blockIdx.x] = sh[255];
    int run = sh[t] - sum;
    if (base + 0 < N) { g_off[base + 0] = run; run += v0; }
    if (base + 1 < N) { g_off[base + 1] = run; run += v1; }
    if (base + 2 < N) { g_off[base + 2] = run; run += v2; }
    if (base + 3 < N) { g_off[base + 3] = run; }
}

__global__ void scan2_kernel(int nb) {
    __shared__ int sh[128];
    int t = threadIdx.x;
    int v = (t < nb) ? g_blocksum[t] : 0;
    sh[t] = v;
    __syncthreads();
    for (int o = 1; o < 128; o <<= 1) {
        int x = (t >= o) ? sh[t - o] : 0;
        __syncthreads();
        sh[t] += x;
        __syncthreads();
    }
    g_blocksum[t] = sh[t] - v;
}

__global__ void scan3_kernel(int N) {
    int i = blockIdx.x * blockDim.x + threadIdx.x;
    if (i < N) g_off[i] += g_blocksum[i >> 10];
}

// ---------------- CSR scatter ----------------
__global__ void scatter_kernel(const void* edge, int E) {
    int e = blockIdx.x * blockDim.x + threadIdx.x;
    if (e >= E) return;
    int is64 = g_edge_is64;
    int s = (int)ld_idx(edge, e, is64);
    int d = (int)ld_idx(edge, (long long)E + e, is64);
    int pos = atomicAdd(&g_cursor[d], 1);
    int2 ent;
    ent.x = s;
    ent.y = __float_as_int(g_deg[s]);
    g_csr[g_off[d] + pos] = ent;
}

// ---------------- layer-1 aggregation on RAW 4-dim features ------------
__global__ void __launch_bounds__(256) agg4_kernel(int N) {
    int d = blockIdx.x * blockDim.x + threadIdx.x;
    if (d >= N) return;
    int off = g_off[d];
    int deg = g_degi[d];
    float dn = g_deg[d];

    float4 x = g_x4[d];
    float4 acc;
    acc.x = x.x * dn; acc.y = x.y * dn; acc.z = x.z * dn; acc.w = x.w * dn;

    int end = off + deg;
    int e0 = off;
    for (; e0 + 4 <= end; e0 += 4) {
        int2 en0 = ldcs_int2(&g_csr[e0 + 0]);
        int2 en1 = ldcs_int2(&g_csr[e0 + 1]);
        int2 en2 = ldcs_int2(&g_csr[e0 + 2]);
        int2 en3 = ldcs_int2(&g_csr[e0 + 3]);
        float4 v0 = g_x4[en0.x];
        float4 v1 = g_x4[en1.x];
        float4 v2 = g_x4[en2.x];
        float4 v3 = g_x4[en3.x];
        float w0 = __int_as_float(en0.y), w1 = __int_as_float(en1.y);
        float w2 = __int_as_float(en2.y), w3 = __int_as_float(en3.y);
        acc.x += w0 * v0.x; acc.y += w0 * v0.y; acc.z += w0 * v0.z; acc.w += w0 * v0.w;
        acc.x += w1 * v1.x; acc.y += w1 * v1.y; acc.z += w1 * v1.z; acc.w += w1 * v1.w;
        acc.x += w2 * v2.x; acc.y += w2 * v2.y; acc.z += w2 * v2.z; acc.w += w2 * v2.w;
        acc.x += w3 * v3.x; acc.y += w3 * v3.y; acc.z += w3 * v3.z; acc.w += w3 * v3.w;
    }
    for (; e0 < end; e0++) {
        int2 en = ldcs_int2(&g_csr[e0]);
        float4 v = g_x4[en.x];
        float w = __int_as_float(en.y);
        acc.x += w * v.x; acc.y += w * v.y; acc.z += w * v.z; acc.w += w * v.w;
    }
    acc.x *= dn; acc.y *= dn; acc.z *= dn; acc.w *= dn;
    g_x4agg[d] = acc;
}

// ---------------- layer-1 transform: (N,4)@(4,128) + bias + relu -------
// tf32-emulated (inputs rounded like the reference's tf32 matmul).
__global__ void transform1_kernel(const float* __restrict__ W0,
                                  const float* __restrict__ b0, int N) {
    int idx = blockIdx.x * blockDim.x + threadIdx.x;
    if (idx >= N * HDIM) return;
    int n = idx >> 7, j = idx & 127;
    float4 x = g_x4agg[n];
    float x0 = to_tf32f(x.x), x1 = to_tf32f(x.y);
    float x2 = to_tf32f(x.z), x3 = to_tf32f(x.w);
    float w0 = to_tf32f(W0[j]);
    float w1 = to_tf32f(W0[HDIM + j]);
    float w2 = to_tf32f(W0[2 * HDIM + j]);
    float w3 = to_tf32f(W0[3 * HDIM + j]);
    float h = x0 * w0;
    h += x1 * w1;
    h += x2 * w2;
    h += x3 * w3;
    h += b0[j];
    stcs_float(&g_buf0[idx], h > 0.0f ? h : 0.0f);
}

// ---------------- fused aggregation + self-loop + bias + relu (H=128) --
// (R10 winner: full width, one warp per dst node, 8-deep gather pipeline)
__global__ void __launch_bounds__(256) agg_kernel(const float* __restrict__ bias, int N) {
    int warp = (blockIdx.x * 256 + threadIdx.x) >> 5;
    int lane = threadIdx.x & 31;
    if (warp >= N) return;
    int d   = warp;
    int off = g_off[d];
    int deg = g_degi[d];
    float dn = g_deg[d];

    float4 h = ((const float4*)&g_buf1[(size_t)d * HDIM])[lane];
    float4 acc;
    acc.x = h.x * dn; acc.y = h.y * dn; acc.z = h.z * dn; acc.w = h.w * dn;

    int end = off + deg;
    int e0 = off;
    for (; e0 + 8 <= end; e0 += 8) {
        int2 en0 = ldcs_int2(&g_csr[e0 + 0]);
        int2 en1 = ldcs_int2(&g_csr[e0 + 1]);
        int2 en2 = ldcs_int2(&g_csr[e0 + 2]);
        int2 en3 = ldcs_int2(&g_csr[e0 + 3]);
        int2 en4 = ldcs_int2(&g_csr[e0 + 4]);
        int2 en5 = ldcs_int2(&g_csr[e0 + 5]);
        int2 en6 = ldcs_int2(&g_csr[e0 + 6]);
        int2 en7 = ldcs_int2(&g_csr[e0 + 7]);
        float4 v0 = ((const float4*)&g_buf1[(size_t)en0.x * HDIM])[lane];
        float4 v1 = ((const float4*)&g_buf1[(size_t)en1.x * HDIM])[lane];
        float4 v2 = ((const float4*)&g_buf1[(size_t)en2.x * HDIM])[lane];
        float4 v3 = ((const float4*)&g_buf1[(size_t)en3.x * HDIM])[lane];
        float4 v4 = ((const float4*)&g_buf1[(size_t)en4.x * HDIM])[lane];
        float4 v5 = ((const float4*)&g_buf1[(size_t)en5.x * HDIM])[lane];
        float4 v6 = ((const float4*)&g_buf1[(size_t)en6.x * HDIM])[lane];
        float4 v7 = ((const float4*)&g_buf1[(size_t)en7.x * HDIM])[lane];
        float w0 = __int_as_float(en0.y), w1 = __int_as_float(en1.y);
        float w2 = __int_as_float(en2.y), w3 = __int_as_float(en3.y);
        float w4 = __int_as_float(en4.y), w5 = __int_as_float(en5.y);
        float w6 = __int_as_float(en6.y), w7 = __int_as_float(en7.y);
        acc.x += w0 * v0.x; acc.y += w0 * v0.y; acc.z += w0 * v0.z; acc.w += w0 * v0.w;
        acc.x += w1 * v1.x; acc.y += w1 * v1.y; acc.z += w1 * v1.z; acc.w += w1 * v1.w;
        acc.x += w2 * v2.x; acc.y += w2 * v2.y; acc.z += w2 * v2.z; acc.w += w2 * v2.w;
        acc.x += w3 * v3.x; acc.y += w3 * v3.y; acc.z += w3 * v3.z; acc.w += w3 * v3.w;
        acc.x += w4 * v4.x; acc.y += w4 * v4.y; acc.z += w4 * v4.z; acc.w += w4 * v4.w;
        acc.x += w5 * v5.x; acc.y += w5 * v5.y; acc.z += w5 * v5.z; acc.w += w5 * v5.w;
        acc.x += w6 * v6.x; acc.y += w6 * v6.y; acc.z += w6 * v6.z; acc.w += w6 * v6.w;
        acc.x += w7 * v7.x; acc.y += w7 * v7.y; acc.z += w7 * v7.z; acc.w += w7 * v7.w;
    }
    for (; e0 + 4 <= end; e0 += 4) {
        int2 en0 = ldcs_int2(&g_csr[e0 + 0]);
        int2 en1 = ldcs_int2(&g_csr[e0 + 1]);
        int2 en2 = ldcs_int2(&g_csr[e0 + 2]);
        int2 en3 = ldcs_int2(&g_csr[e0 + 3]);
        float4 v0 = ((const float4*)&g_buf1[(size_t)en0.x * HDIM])[lane];
        float4 v1 = ((const float4*)&g_buf1[(size_t)en1.x * HDIM])[lane];
        float4 v2 = ((const float4*)&g_buf1[(size_t)en2.x * HDIM])[lane];
        float4 v3 = ((const float4*)&g_buf1[(size_t)en3.x * HDIM])[lane];
        float w0 = __int_as_float(en0.y), w1 = __int_as_float(en1.y);
        float w2 = __int_as_float(en2.y), w3 = __int_as_float(en3.y);
        acc.x += w0 * v0.x; acc.y += w0 * v0.y; acc.z += w0 * v0.z; acc.w += w0 * v0.w;
        acc.x += w1 * v1.x; acc.y += w1 * v1.y; acc.z += w1 * v1.z; acc.w += w1 * v1.w;
        acc.x += w2 * v2.x; acc.y += w2 * v2.y; acc.z += w2 * v2.z; acc.w += w2 * v2.w;
        acc.x += w3 * v3.x; acc.y += w3 * v3.y; acc.z += w3 * v3.z; acc.w += w3 * v3.w;
    }
    for (; e0 < end; e0++) {
        int2 en = ldcs_int2(&g_csr[e0]);
        float4 v = ((const float4*)&g_buf1[(size_t)en.x * HDIM])[lane];
        float w = __int_as_float(en.y);
        acc.x += w * v.x; acc.y += w * v.y; acc.z += w * v.z; acc.w += w * v.w;
    }

    float4 b = ((const float4*)bias)[lane];
    float4 r;
    r.x = fmaxf(acc.x * dn + b.x, 0.0f);
    r.y = fmaxf(acc.y * dn + b.y, 0.0f);
    r.z = fmaxf(acc.z * dn + b.z, 0.0f);
    r.w = fmaxf(acc.w * dn + b.w, 0.0f);
    stcs_float4(&((float4*)&g_buf0[(size_t)d * HDIM])[lane], r);
}

// ---------------- layers 2/3: TF32 tensor-core GEMM --------------------
// (N,128)@(128,128) via mma.sync.m16n8k8.tf32 — the same arithmetic
// family the JAX reference uses for f32 matmuls (tf32 inputs, fp32 acc).
// Block = 128 threads (4 warps) x 64 rows. Warp tile: 16 rows x 128 cols.
// Xs padded to 132 floats/row, Ws padded to 136 -> conflict-free frags.
#define GROWS 64
__global__ void __launch_bounds__(128) gemm_kernel(const float* __restrict__ W, int N) {
    __shared__ float Xs[GROWS][132];   // 33 KB
    __shared__ float Ws[8][136];       // 4.25 KB
    int n0   = blockIdx.x * GROWS;
    int tid  = threadIdx.x;
    int warp = tid >> 5;
    int lane = tid & 31;

    // stage X tile (tf32-rounded); one row per iteration, col = tid
    for (int r = 0; r < GROWS; r++) {
        int n = n0 + r;
        float v = (n < N) ? g_buf0[(size_t)n * HDIM + tid] : 0.0f;
        Xs[r][tid] = to_tf32f(v);
    }

    float acc[16][4];
    #pragma unroll
    for (int nt = 0; nt < 16; nt++) {
        acc[nt][0] = 0.f; acc[nt][1] = 0.f; acc[nt][2] = 0.f; acc[nt][3] = 0.f;
    }

    int r0 = warp * 16;
    int qr = lane >> 2;       // 0..7
    int qc = lane & 3;        // 0..3

    for (int ks = 0; ks < 16; ks++) {
        __syncthreads();      // prior compute done (and Xs staged on ks=0)
        #pragma unroll
        for (int i = 0; i < 8; i++)
            Ws[i][tid] = to_tf32f(W[(ks * 8 + i) * HDIM + tid]);
        __syncthreads();

        int acol = ks * 8 + qc;
        unsigned int a0 = __float_as_uint(Xs[r0 + qr][acol]);
        unsigned int a1 = __float_as_uint(Xs[r0 + qr + 8][acol]);
        unsigned int a2 = __float_as_uint(Xs[r0 + qr][acol + 4]);
        unsigned int a3 = __float_as_uint(Xs[r0 + qr + 8][acol + 4]);

        #pragma unroll
        for (int nt = 0; nt < 16; nt++) {
            unsigned int b0 = __float_as_uint(Ws[qc][nt * 8 + qr]);
            unsigned int b1 = __float_as_uint(Ws[qc + 4][nt * 8 + qr]);
            asm volatile(
                "mma.sync.aligned.m16n8k8.row.col.f32.tf32.tf32.f32 "
                "{%0,%1,%2,%3}, {%4,%5,%6,%7}, {%8,%9}, {%0,%1,%2,%3};"
                : "+f"(acc[nt][0]), "+f"(acc[nt][1]),
                  "+f"(acc[nt][2]), "+f"(acc[nt][3])
                : "r"(a0), "r"(a1), "r"(a2), "r"(a3), "r"(b0), "r"(b1));
        }
    }

    // store: c0/c1 -> row r0+qr, cols nt*8 + 2qc, +1 ; c2/c3 -> row +8
    int rowA = n0 + r0 + qr;
    int rowB = rowA + 8;
    #pragma unroll
    for (int nt = 0; nt < 16; nt++) {
        int col = nt * 8 + 2 * qc;
        if (rowA < N) {
            float2 v = make_float2(acc[nt][0], acc[nt][1]);
            *reinterpret_cast<float2*>(&g_buf1[(size_t)rowA * HDIM + col]) = v;
        }
        if (rowB < N) {
            float2 v = make_float2(acc[nt][2], acc[nt][3]);
            *reinterpret_cast<float2*>(&g_buf1[(size_t)rowB * HDIM + col]) = v;
        }
    }
}

// ---------------- pooling ----------------
__global__ void pool_zero_kernel() {
    int i = blockIdx.x * blockDim.x + threadIdx.x;
    if (i < NGRAPH * HDIM) g_pool[i] = 0.0f;
    if (i < NGRAPH) g_cnt[i] = 0.0f;
}

#define POOL_NODES 512
__global__ void __launch_bounds__(128) pool_acc_kernel(const void* batch, int N) {
    int j  = threadIdx.x;
    int n0 = blockIdx.x * POOL_NODES;
    int n1 = min(n0 + POOL_NODES, N);
    int is64 = g_batch_is64;
    double acc = 0.0;
    float cnt = 0.0f;
    int cur = -1;
    for (int n = n0; n < n1; n++) {
        int g = (int)ld_idx(batch, n, is64);
        if (g != cur) {
            if (cur >= 0) {
                atomicAdd(&g_pool[cur * HDIM + j], (float)acc);
                if (j == 0) atomicAdd(&g_cnt[cur], cnt);
            }
            cur = g; acc = 0.0; cnt = 0.0f;
        }
        acc += (double)ldcs_float(&g_buf0[(size_t)n * HDIM + j]);
        cnt += 1.0f;
    }
    if (cur >= 0) {
        atomicAdd(&g_pool[cur * HDIM + j], (float)acc);
        if (j == 0) atomicAdd(&g_cnt[cur], cnt);
    }
}

// ---------------- head: mean, linear(128->8) in tf32-emulated fp32, ----
// ---------------- softmax in double --------------------------------
__global__ void final_kernel(const float* __restrict__ linW,
                             const float* __restrict__ linb,
                             float* __restrict__ out) {
    int t = threadIdx.x;             // 512 = 64 graphs * 8 experts
    int g = t >> 3, e = t & 7;
    float c = fmaxf(g_cnt[g], 1.0f);
    float acc = 0.0f;
    #pragma unroll 8
    for (int k = 0; k < HDIM; k++) {
        float p = to_tf32f(g_pool[g * HDIM + k] / c);
        float w = to_tf32f(linW[k * 8 + e]);
        acc += p * w;
    }
    double logit = (double)acc + (double)linb[e];
    double m = logit;
    for (int o = 4; o >= 1; o >>= 1) {
        double other = __shfl_xor_sync(0xFFFFFFFFu, m, o);
        m = fmax(m, other);
    }
    double ex = exp(logit - m);
    double s = ex;
    for (int o = 4; o >= 1; o >>= 1)
        s += __shfl_xor_sync(0xFFFFFFFFu, s, o);
    out[t] = (float)(ex / s);
}

// ---------------- launch ----------------
extern "C" void kernel_launch(void* const* d_in, const int* in_sizes, int n_in,
                              void* d_out, int out_size) {
    const float* an   = (const float*)d_in[0];
    const float* pos  = (const float*)d_in[1];
    const float* W0   = (const float*)d_in[2];
    const float* b0   = (const float*)d_in[3];
    const float* W1   = (const float*)d_in[4];
    const float* b1   = (const float*)d_in[5];
    const float* W2   = (const float*)d_in[6];
    const float* b2   = (const float*)d_in[7];
    const float* linW = (const float*)d_in[8];
    const float* linb = (const float*)d_in[9];
    const void*  edge = d_in[10];
    const void*  batch= d_in[11];
    int N = in_sizes[0];
    int E = in_sizes[10] / 2;
    float* out = (float*)d_out;

    // prologue: degrees, norms, features, CSR
    detect_zero_kernel<<<(N + 255) / 256, 256>>>(edge, batch, N);
    count_deg_kernel<<<(E + 255) / 256, 256>>>(edge, E);
    dinv_kernel<<<(N + 255) / 256, 256>>>(an, pos, N);
    int nb = (N + 1023) / 1024;
    scan1_kernel<<<nb, 256>>>(N);
    scan2_kernel<<<1, 128>>>(nb);
    scan3_kernel<<<(N + 255) / 256, 256>>>(N);
    scatter_kernel<<<(E + 255) / 256, 256>>>(edge, E);

    int nh = N * HDIM;
    int agg_grid = (N + 7) / 8;
    // layer 1: aggregate raw 4-dim features, then transform+bias+relu
    agg4_kernel<<<(N + 255) / 256, 256>>>(N);
    transform1_kernel<<<(nh + 255) / 256, 256>>>(W0, b0, N);
    // layer 2
    gemm_kernel<<<(N + GROWS - 1) / GROWS, 128>>>(W1, N);
    agg_kernel<<<agg_grid, 256>>>(b1, N);
    // layer 3
    gemm_kernel<<<(N + GROWS - 1) / GROWS, 128>>>(W2, N);
    agg_kernel<<<agg_grid, 256>>>(b2, N);
    // pool + head
    pool_zero_kernel<<<(NGRAPH * HDIM + 255) / 256, 256>>>();
    pool_acc_kernel<<<(N + POOL_NODES - 1) / POOL_NODES, 128>>>(batch, N);
    final_kernel<<<1, 512>>>(linW, linb, out);
}

// round 14
// speedup vs baseline: 1.2515x; 1.0585x over previous
#include <cuda_runtime.h>
#include <cuda_bf16.h>
#include <cstdint>
#include <math.h>

#define HDIM 128
#define MAXN 100608
#define MAXE 1700000
#define NGRAPH 64

// ---------------- device scratch (no allocation allowed) ----------------
__device__ float  g_deg[MAXN];                  // dinv = 1/sqrt(deg)
__device__ int    g_degi[MAXN];                 // in-degree (without self loop)
__device__ int    g_off[MAXN];                  // CSR offsets (exclusive scan)
__device__ int    g_cursor[MAXN];               // scatter cursors
__device__ int    g_blocksum[128];              // scan partials
__device__ int2   g_csr[MAXE];                  // {src, dinv[src] as bits}
__device__ float4 g_x4[MAXN];                   // packed input features [a,px,py,pz]
__device__ float4 g_x4agg[MAXN];                // aggregated input features
__device__ float  g_buf0[(size_t)MAXN * HDIM];  // X / AGG buffer
__device__ float  g_buf1[(size_t)MAXN * HDIM];  // H (transformed) buffer
__device__ float  g_pool[NGRAPH * HDIM];
__device__ float  g_cnt[NGRAPH];
__device__ int    g_edge_is64;
__device__ int    g_batch_is64;

// ---------------- tf32 helpers -----------------------------------------
__device__ __forceinline__ unsigned int to_tf32(float v) {
    unsigned int t;
    asm("cvt.rna.tf32.f32 %0, %1;" : "=r"(t) : "f"(v));
    return t;
}
__device__ __forceinline__ float to_tf32f(float v) {
    return __uint_as_float(to_tf32(v));
}

// ---------------- streaming (evict-first) access helpers ----------------
__device__ __forceinline__ int2 ldcs_int2(const int2* p) {
    int2 r;
    asm("ld.global.cs.v2.s32 {%0, %1}, [%2];" : "=r"(r.x), "=r"(r.y) : "l"(p));
    return r;
}
__device__ __forceinline__ void stcs_float4(float4* p, float4 v) {
    asm("st.global.cs.v4.f32 [%0], {%1, %2, %3, %4};"
        :: "l"(p), "f"(v.x), "f"(v.y), "f"(v.z), "f"(v.w) : "memory");
}
__device__ __forceinline__ float ldcs_float(const float* p) {
    float r;
    asm("ld.global.cs.f32 %0, [%1];" : "=f"(r) : "l"(p));
    return r;
}

// ---------------- index helper: int64 vs int32 storage ----------------
__device__ __forceinline__ long long ld_idx(const void* p, long long i, int is64) {
    if (is64) return ((const long long*)p)[i];
    return (long long)((const int*)p)[i];
}

// ---------------- detect dtypes + zero degree/pool arrays (merged) -----
__global__ void detect_zero_kernel(const void* edge, const void* batch, int N) {
    int i = blockIdx.x * blockDim.x + threadIdx.x;
    if (i < N) { g_degi[i] = 0; g_cursor[i] = 0; }
    if (i < NGRAPH * HDIM) g_pool[i] = 0.0f;
    if (i < NGRAPH) g_cnt[i] = 0.0f;
    if (blockIdx.x == 0 && threadIdx.x < 64) {
        int lane = threadIdx.x & 31;
        int w    = threadIdx.x >> 5;
        const long long* p = (w == 0) ? (const long long*)edge
                                      : (const long long*)batch;
        long long v0 = p[lane * 2];
        long long v1 = p[lane * 2 + 1];
        int bad = (v0 < 0) | (v0 >= (1LL << 31)) | (v1 < 0) | (v1 >= (1LL << 31));
        unsigned m = __ballot_sync(0xFFFFFFFFu, bad);
        if (lane == 0) {
            int ok = (m == 0u);
            if (w == 0) g_edge_is64 = ok; else g_batch_is64 = ok;
        }
    }
}

__global__ void count_deg_kernel(const void* edge, int E) {
    int e = blockIdx.x * blockDim.x + threadIdx.x;
    if (e >= E) return;
    int is64 = g_edge_is64;
    int d = (int)ld_idx(edge, (long long)E + e, is64);
    atomicAdd(&g_degi[d], 1);
}

// also packs x4 = [a, pos] (fused; same launch shape)
__global__ void dinv_kernel(const float* __restrict__ an,
                            const float* __restrict__ pos, int N) {
    int i = blockIdx.x * blockDim.x + threadIdx.x;
    if (i >= N) return;
    g_deg[i] = (float)(1.0 / sqrt((double)(g_degi[i] + 1)));
    float4 x;
    x.x = an[i];
    x.y = pos[3 * i + 0];
    x.z = pos[3 * i + 1];
    x.w = pos[3 * i + 2];
    g_x4[i] = x;
}

// ---------------- exclusive prefix scan of g_degi -> g_off ----------------
__global__ void __launch_bounds__(256) scan1_kernel(int N) {
    __shared__ int sh[256];
    int t = threadIdx.x;
    int base = blockIdx.x * 1024 + t * 4;
    int v0 = (base + 0 < N) ? g_degi[base + 0] : 0;
    int v1 = (base + 1 < N) ? g_degi[base + 1] : 0;
    int v2 = (base + 2 < N) ? g_degi[base + 2] : 0;
    int v3 = (base + 3 < N) ? g_degi[base + 3] : 0;
    int sum = v0 + v1 + v2 + v3;
    sh[t] = sum;
    __syncthreads();
    for (int o = 1; o < 256; o <<= 1) {
        int x = (t >= o) ? sh[t - o] : 0;
        __syncthreads();
        sh[t] += x;
        __syncthreads();
    }
    if (t == 255) g_blocksum[blockIdx.x] = sh[255];
    int run = sh[t] - sum;
    if (base + 0 < N) { g_off[base + 0] = run; run += v0; }
    if (base + 1 < N) { g_off[base + 1] = run; run += v1; }
    if (base + 2 < N) { g_off[base + 2] = run; run += v2; }
    if (base + 3 < N) { g_off[base + 3] = run; }
}

__global__ void scan2_kernel(int nb) {
    __shared__ int sh[128];
    int t = threadIdx.x;
    int v = (t < nb) ? g_blocksum[t] : 0;
    sh[t] = v;
    __syncthreads();
    for (int o = 1; o < 128; o <<= 1) {
        int x = (t >= o) ? sh[t - o] : 0;
        __syncthreads();
        sh[t] += x;
        __syncthreads();
    }
    g_blocksum[t] = sh[t] - v;
}

__global__ void scan3_kernel(int N) {
    int i = blockIdx.x * blockDim.x + threadIdx.x;
    if (i < N) g_off[i] += g_blocksum[i >> 10];
}

// ---------------- CSR scatter ----------------
__global__ void scatter_kernel(const void* edge, int E) {
    int e = blockIdx.x * blockDim.x + threadIdx.x;
    if (e >= E) return;
    int is64 = g_edge_is64;
    int s = (int)ld_idx(edge, e, is64);
    int d = (int)ld_idx(edge, (long long)E + e, is64);
    int pos = atomicAdd(&g_cursor[d], 1);
    int2 ent;
    ent.x = s;
    ent.y = __float_as_int(g_deg[s]);
    g_csr[g_off[d] + pos] = ent;
}

// ---------------- layer-1 aggregation on RAW 4-dim features ------------
__global__ void __launch_bounds__(256) agg4_kernel(int N) {
    int d = blockIdx.x * blockDim.x + threadIdx.x;
    if (d >= N) return;
    int off = g_off[d];
    int deg = g_degi[d];
    float dn = g_deg[d];

    float4 x = g_x4[d];
    float4 acc;
    acc.x = x.x * dn; acc.y = x.y * dn; acc.z = x.z * dn; acc.w = x.w * dn;

    int end = off + deg;
    int e0 = off;
    for (; e0 + 4 <= end; e0 += 4) {
        int2 en0 = ldcs_int2(&g_csr[e0 + 0]);
        int2 en1 = ldcs_int2(&g_csr[e0 + 1]);
        int2 en2 = ldcs_int2(&g_csr[e0 + 2]);
        int2 en3 = ldcs_int2(&g_csr[e0 + 3]);
        float4 v0 = g_x4[en0.x];
        float4 v1 = g_x4[en1.x];
        float4 v2 = g_x4[en2.x];
        float4 v3 = g_x4[en3.x];
        float w0 = __int_as_float(en0.y), w1 = __int_as_float(en1.y);
        float w2 = __int_as_float(en2.y), w3 = __int_as_float(en3.y);
        acc.x += w0 * v0.x; acc.y += w0 * v0.y; acc.z += w0 * v0.z; acc.w += w0 * v0.w;
        acc.x += w1 * v1.x; acc.y += w1 * v1.y; acc.z += w1 * v1.z; acc.w += w1 * v1.w;
        acc.x += w2 * v2.x; acc.y += w2 * v2.y; acc.z += w2 * v2.z; acc.w += w2 * v2.w;
        acc.x += w3 * v3.x; acc.y += w3 * v3.y; acc.z += w3 * v3.z; acc.w += w3 * v3.w;
    }
    for (; e0 < end; e0++) {
        int2 en = ldcs_int2(&g_csr[e0]);
        float4 v = g_x4[en.x];
        float w = __int_as_float(en.y);
        acc.x += w * v.x; acc.y += w * v.y; acc.z += w * v.z; acc.w += w * v.w;
    }
    acc.x *= dn; acc.y *= dn; acc.z *= dn; acc.w *= dn;
    g_x4agg[d] = acc;
}

// ---------------- fused aggregation + self-loop + bias + relu (H=128) --
// (R10 winner: full width, one warp per dst node, 8-deep gather pipeline)
__global__ void __launch_bounds__(256) agg_kernel(const float* __restrict__ bias, int N) {
    int warp = (blockIdx.x * 256 + threadIdx.x) >> 5;
    int lane = threadIdx.x & 31;
    if (warp >= N) return;
    int d   = warp;
    int off = g_off[d];
    int deg = g_degi[d];
    float dn = g_deg[d];

    float4 h = ((const float4*)&g_buf1[(size_t)d * HDIM])[lane];
    float4 acc;
    acc.x = h.x * dn; acc.y = h.y * dn; acc.z = h.z * dn; acc.w = h.w * dn;

    int end = off + deg;
    int e0 = off;
    for (; e0 + 8 <= end; e0 += 8) {
        int2 en0 = ldcs_int2(&g_csr[e0 + 0]);
        int2 en1 = ldcs_int2(&g_csr[e0 + 1]);
        int2 en2 = ldcs_int2(&g_csr[e0 + 2]);
        int2 en3 = ldcs_int2(&g_csr[e0 + 3]);
        int2 en4 = ldcs_int2(&g_csr[e0 + 4]);
        int2 en5 = ldcs_int2(&g_csr[e0 + 5]);
        int2 en6 = ldcs_int2(&g_csr[e0 + 6]);
        int2 en7 = ldcs_int2(&g_csr[e0 + 7]);
        float4 v0 = ((const float4*)&g_buf1[(size_t)en0.x * HDIM])[lane];
        float4 v1 = ((const float4*)&g_buf1[(size_t)en1.x * HDIM])[lane];
        float4 v2 = ((const float4*)&g_buf1[(size_t)en2.x * HDIM])[lane];
        float4 v3 = ((const float4*)&g_buf1[(size_t)en3.x * HDIM])[lane];
        float4 v4 = ((const float4*)&g_buf1[(size_t)en4.x * HDIM])[lane];
        float4 v5 = ((const float4*)&g_buf1[(size_t)en5.x * HDIM])[lane];
        float4 v6 = ((const float4*)&g_buf1[(size_t)en6.x * HDIM])[lane];
        float4 v7 = ((const float4*)&g_buf1[(size_t)en7.x * HDIM])[lane];
        float w0 = __int_as_float(en0.y), w1 = __int_as_float(en1.y);
        float w2 = __int_as_float(en2.y), w3 = __int_as_float(en3.y);
        float w4 = __int_as_float(en4.y), w5 = __int_as_float(en5.y);
        float w6 = __int_as_float(en6.y), w7 = __int_as_float(en7.y);
        acc.x += w0 * v0.x; acc.y += w0 * v0.y; acc.z += w0 * v0.z; acc.w += w0 * v0.w;
        acc.x += w1 * v1.x; acc.y += w1 * v1.y; acc.z += w1 * v1.z; acc.w += w1 * v1.w;
        acc.x += w2 * v2.x; acc.y += w2 * v2.y; acc.z += w2 * v2.z; acc.w += w2 * v2.w;
        acc.x += w3 * v3.x; acc.y += w3 * v3.y; acc.z += w3 * v3.z; acc.w += w3 * v3.w;
        acc.x += w4 * v4.x; acc.y += w4 * v4.y; acc.z += w4 * v4.z; acc.w += w4 * v4.w;
        acc.x += w5 * v5.x; acc.y += w5 * v5.y; acc.z += w5 * v5.z; acc.w += w5 * v5.w;
        acc.x += w6 * v6.x; acc.y += w6 * v6.y; acc.z += w6 * v6.z; acc.w += w6 * v6.w;
        acc.x += w7 * v7.x; acc.y += w7 * v7.y; acc.z += w7 * v7.z; acc.w += w7 * v7.w;
    }
    for (; e0 + 4 <= end; e0 += 4) {
        int2 en0 = ldcs_int2(&g_csr[e0 + 0]);
        int2 en1 = ldcs_int2(&g_csr[e0 + 1]);
        int2 en2 = ldcs_int2(&g_csr[e0 + 2]);
        int2 en3 = ldcs_int2(&g_csr[e0 + 3]);
        float4 v0 = ((const float4*)&g_buf1[(size_t)en0.x * HDIM])[lane];
        float4 v1 = ((const float4*)&g_buf1[(size_t)en1.x * HDIM])[lane];
        float4 v2 = ((const float4*)&g_buf1[(size_t)en2.x * HDIM])[lane];
        float4 v3 = ((const float4*)&g_buf1[(size_t)en3.x * HDIM])[lane];
        float w0 = __int_as_float(en0.y), w1 = __int_as_float(en1.y);
        float w2 = __int_as_float(en2.y), w3 = __int_as_float(en3.y);
        acc.x += w0 * v0.x; acc.y += w0 * v0.y; acc.z += w0 * v0.z; acc.w += w0 * v0.w;
        acc.x += w1 * v1.x; acc.y += w1 * v1.y; acc.z += w1 * v1.z; acc.w += w1 * v1.w;
        acc.x += w2 * v2.x; acc.y += w2 * v2.y; acc.z += w2 * v2.z; acc.w += w2 * v2.w;
        acc.x += w3 * v3.x; acc.y += w3 * v3.y; acc.z += w3 * v3.z; acc.w += w3 * v3.w;
    }
    for (; e0 < end; e0++) {
        int2 en = ldcs_int2(&g_csr[e0]);
        float4 v = ((const float4*)&g_buf1[(size_t)en.x * HDIM])[lane];
        float w = __int_as_float(en.y);
        acc.x += w * v.x; acc.y += w * v.y; acc.z += w * v.z; acc.w += w * v.w;
    }

    float4 b = ((const float4*)bias)[lane];
    float4 r;
    r.x = fmaxf(acc.x * dn + b.x, 0.0f);
    r.y = fmaxf(acc.y * dn + b.y, 0.0f);
    r.z = fmaxf(acc.z * dn + b.z, 0.0f);
    r.w = fmaxf(acc.w * dn + b.w, 0.0f);
    stcs_float4(&((float4*)&g_buf0[(size_t)d * HDIM])[lane], r);
}

// ---------------- TF32 tensor-core GEMM core ---------------------------
// Computes D = Xs @ W for one 64-row tile; Xs already staged (tf32).
// Block = 128 threads (4 warps). Warp tile: 16 rows x 128 cols.
__device__ __forceinline__ void gemm_mma_body(
    float (*Xs)[132], float (*Ws)[136],
    const float* __restrict__ W, int n0, int N, int tid)
{
    int warp = tid >> 5;
    int lane = tid & 31;
    float acc[16][4];
    #pragma unroll
    for (int nt = 0; nt < 16; nt++) {
        acc[nt][0] = 0.f; acc[nt][1] = 0.f; acc[nt][2] = 0.f; acc[nt][3] = 0.f;
    }

    int r0 = warp * 16;
    int qr = lane >> 2;       // 0..7
    int qc = lane & 3;        // 0..3

    for (int ks = 0; ks < 16; ks++) {
        __syncthreads();      // prior compute done (and Xs staged on ks=0)
        #pragma unroll
        for (int i = 0; i < 8; i++)
            Ws[i][tid] = to_tf32f(W[(ks * 8 + i) * HDIM + tid]);
        __syncthreads();

        int acol = ks * 8 + qc;
        unsigned int a0 = __float_as_uint(Xs[r0 + qr][acol]);
        unsigned int a1 = __float_as_uint(Xs[r0 + qr + 8][acol]);
        unsigned int a2 = __float_as_uint(Xs[r0 + qr][acol + 4]);
        unsigned int a3 = __float_as_uint(Xs[r0 + qr + 8][acol + 4]);

        #pragma unroll
        for (int nt = 0; nt < 16; nt++) {
            unsigned int b0 = __float_as_uint(Ws[qc][nt * 8 + qr]);
            unsigned int b1 = __float_as_uint(Ws[qc + 4][nt * 8 + qr]);
            asm volatile(
                "mma.sync.aligned.m16n8k8.row.col.f32.tf32.tf32.f32 "
                "{%0,%1,%2,%3}, {%4,%5,%6,%7}, {%8,%9}, {%0,%1,%2,%3};"
                : "+f"(acc[nt][0]), "+f"(acc[nt][1]),
                  "+f"(acc[nt][2]), "+f"(acc[nt][3])
                : "r"(a0), "r"(a1), "r"(a2), "r"(a3), "r"(b0), "r"(b1));
        }
    }

    int rowA = n0 + r0 + qr;
    int rowB = rowA + 8;
    #pragma unroll
    for (int nt = 0; nt < 16; nt++) {
        int col = nt * 8 + 2 * qc;
        if (rowA < N) {
            float2 v = make_float2(acc[nt][0], acc[nt][1]);
            *reinterpret_cast<float2*>(&g_buf1[(size_t)rowA * HDIM + col]) = v;
        }
        if (rowB < N) {
            float2 v = make_float2(acc[nt][2], acc[nt][3]);
            *reinterpret_cast<float2*>(&g_buf1[(size_t)rowB * HDIM + col]) = v;
        }
    }
}

#define GROWS 64

// layer-2 gemm: stages X by computing layer-1 transform on the fly:
// Xs[r][j] = tf32( relu( sum_k tf32(x4agg[r].k) * tf32(W0[k][j]) + b0[j] ) )
// (identical arithmetic to the former transform1_kernel, minus 102MB of
//  buf0 traffic and one launch)
__global__ void __launch_bounds__(128) gemm1_kernel(const float* __restrict__ W0,
                                                    const float* __restrict__ b0,
                                                    const float* __restrict__ W1, int N) {
    __shared__ float Xs[GROWS][132];   // 33 KB
    __shared__ float Ws[8][136];       // 4.25 KB
    int n0  = blockIdx.x * GROWS;
    int tid = threadIdx.x;

    float w0 = to_tf32f(W0[tid]);
    float w1 = to_tf32f(W0[HDIM + tid]);
    float w2 = to_tf32f(W0[2 * HDIM + tid]);
    float w3 = to_tf32f(W0[3 * HDIM + tid]);
    float bb = b0[tid];

    for (int r = 0; r < GROWS; r++) {
        int n = n0 + r;
        float4 x = (n < N) ? g_x4agg[n] : make_float4(0.f, 0.f, 0.f, 0.f);
        float h = to_tf32f(x.x) * w0;
        h += to_tf32f(x.y) * w1;
        h += to_tf32f(x.z) * w2;
        h += to_tf32f(x.w) * w3;
        h += bb;
        Xs[r][tid] = to_tf32f(h > 0.0f ? h : 0.0f);
    }
    gemm_mma_body(Xs, Ws, W1, n0, N, tid);
}

// layer-3 gemm: stages X from buf0 (layer-2 agg output)
__global__ void __launch_bounds__(128) gemm2_kernel(const float* __restrict__ W, int N) {
    __shared__ float Xs[GROWS][132];
    __shared__ float Ws[8][136];
    int n0  = blockIdx.x * GROWS;
    int tid = threadIdx.x;

    for (int r = 0; r < GROWS; r++) {
        int n = n0 + r;
        float v = (n < N) ? g_buf0[(size_t)n * HDIM + tid] : 0.0f;
        Xs[r][tid] = to_tf32f(v);
    }
    gemm_mma_body(Xs, Ws, W, n0, N, tid);
}

// ---------------- pooling ----------------
#define POOL_NODES 512
__global__ void __launch_bounds__(128) pool_acc_kernel(const void* batch, int N) {
    int j  = threadIdx.x;
    int n0 = blockIdx.x * POOL_NODES;
    int n1 = min(n0 + POOL_NODES, N);
    int is64 = g_batch_is64;
    double acc = 0.0;
    float cnt = 0.0f;
    int cur = -1;
    for (int n = n0; n < n1; n++) {
        int g = (int)ld_idx(batch, n, is64);
        if (g != cur) {
            if (cur >= 0) {
                atomicAdd(&g_pool[cur * HDIM + j], (float)acc);
                if (j == 0) atomicAdd(&g_cnt[cur], cnt);
            }
            cur = g; acc = 0.0; cnt = 0.0f;
        }
        acc += (double)ldcs_float(&g_buf0[(size_t)n * HDIM + j]);
        cnt += 1.0f;
    }
    if (cur >= 0) {
        atomicAdd(&g_pool[cur * HDIM + j], (float)acc);
        if (j == 0) atomicAdd(&g_cnt[cur], cnt);
    }
}

// ---------------- head: mean, linear(128->8) tf32-emulated, ------------
// ---------------- softmax in double ------------------------------------
__global__ void final_kernel(const float* __restrict__ linW,
                             const float* __restrict__ linb,
                             float* __restrict__ out) {
    int t = threadIdx.x;             // 512 = 64 graphs * 8 experts
    int g = t >> 3, e = t & 7;
    float c = fmaxf(g_cnt[g], 1.0f);
    float acc = 0.0f;
    #pragma unroll 8
    for (int k = 0; k < HDIM; k++) {
        float p = to_tf32f(g_pool[g * HDIM + k] / c);
        float w = to_tf32f(linW[k * 8 + e]);
        acc += p * w;
    }
    double logit = (double)acc + (double)linb[e];
    double m = logit;
    for (int o = 4; o >= 1; o >>= 1) {
        double other = __shfl_xor_sync(0xFFFFFFFFu, m, o);
        m = fmax(m, other);
    }
    double ex = exp(logit - m);
    double s = ex;
    for (int o = 4; o >= 1; o >>= 1)
        s += __shfl_xor_sync(0xFFFFFFFFu, s, o);
    out[t] = (float)(ex / s);
}

// ---------------- launch ----------------
extern "C" void kernel_launch(void* const* d_in, const int* in_sizes, int n_in,
                              void* d_out, int out_size) {
    const float* an   = (const float*)d_in[0];
    const float* pos  = (const float*)d_in[1];
    const float* W0   = (const float*)d_in[2];
    const float* b0   = (const float*)d_in[3];
    const float* W1   = (const float*)d_in[4];
    const float* b1   = (const float*)d_in[5];
    const float* W2   = (const float*)d_in[6];
    const float* b2   = (const float*)d_in[7];
    const float* linW = (const float*)d_in[8];
    const float* linb = (const float*)d_in[9];
    const void*  edge = d_in[10];
    const void*  batch= d_in[11];
    int N = in_sizes[0];
    int E = in_sizes[10] / 2;
    float* out = (float*)d_out;

    // prologue: zero + detect, degrees, norms, CSR
    detect_zero_kernel<<<(N + 255) / 256, 256>>>(edge, batch, N);
    count_deg_kernel<<<(E + 255) / 256, 256>>>(edge, E);
    dinv_kernel<<<(N + 255) / 256, 256>>>(an, pos, N);
    int nb = (N + 1023) / 1024;
    scan1_kernel<<<nb, 256>>>(N);
    scan2_kernel<<<1, 128>>>(nb);
    scan3_kernel<<<(N + 255) / 256, 256>>>(N);
    scatter_kernel<<<(E + 255) / 256, 256>>>(edge, E);

    int agg_grid = (N + 7) / 8;
    // layer 1: aggregate raw 4-dim features (transform fused into gemm1)
    agg4_kernel<<<(N + 255) / 256, 256>>>(N);
    // layer 2 (stages layer-1 transform on the fly)
    gemm1_kernel<<<(N + GROWS - 1) / GROWS, 128>>>(W0, b0, W1, N);
    agg_kernel<<<agg_grid, 256>>>(b1, N);
    // layer 3
    gemm2_kernel<<<(N + GROWS - 1) / GROWS, 128>>>(W2, N);
    agg_kernel<<<agg_grid, 256>>>(b2, N);
    // pool + head
    pool_acc_kernel<<<(N + POOL_NODES - 1) / POOL_NODES, 128>>>(batch, N);
    final_kernel<<<1, 512>>>(linW, linb, out);
}

// round 15
// speedup vs baseline: 2.2770x; 1.8195x over previous
#include <cuda_runtime.h>
#include <cuda_bf16.h>
#include <cstdint>
#include <math.h>

#define HDIM 128
#define MAXN 100608
#define MAXE 1700000
#define NGRAPH 64

// ---------------- device scratch (no allocation allowed) ----------------
__device__ float  g_deg[MAXN];                  // dinv = 1/sqrt(deg)
__device__ int    g_degi[MAXN];                 // in-degree (without self loop)
__device__ int    g_off[MAXN];                  // CSR offsets (exclusive scan)
__device__ int    g_cursor[MAXN];               // scatter cursors
__device__ int    g_blocksum[128];              // scan partials
__device__ int2   g_csr[MAXE];                  // {src, dinv[src] as bits}
__device__ float4 g_x4[MAXN];                   // packed input features [a,px,py,pz]
__device__ float4 g_x4agg[MAXN];                // aggregated input features
__device__ float  g_buf0[(size_t)MAXN * HDIM];  // X / AGG buffer
__device__ float  g_buf1[(size_t)MAXN * HDIM];  // H (transformed) buffer
__device__ float  g_pool[NGRAPH * HDIM];
__device__ float  g_cnt[NGRAPH];
__device__ int    g_edge_is64;
__device__ int    g_batch_is64;

// ---------------- tf32 helpers -----------------------------------------
__device__ __forceinline__ unsigned int to_tf32(float v) {
    unsigned int t;
    asm("cvt.rna.tf32.f32 %0, %1;" : "=r"(t) : "f"(v));
    return t;
}
__device__ __forceinline__ float to_tf32f(float v) {
    return __uint_as_float(to_tf32(v));
}

// ---------------- streaming / atomic access helpers ---------------------
__device__ __forceinline__ int2 ldcs_int2(const int2* p) {
    int2 r;
    asm("ld.global.cs.v2.s32 {%0, %1}, [%2];" : "=r"(r.x), "=r"(r.y) : "l"(p));
    return r;
}
__device__ __forceinline__ void stcs_float4(float4* p, float4 v) {
    asm("st.global.cs.v4.f32 [%0], {%1, %2, %3, %4};"
        :: "l"(p), "f"(v.x), "f"(v.y), "f"(v.z), "f"(v.w) : "memory");
}
__device__ __forceinline__ void red_add_f32(float* p, float v) {
    asm volatile("red.global.add.f32 [%0], %1;" :: "l"(p), "f"(v) : "memory");
}

// ---------------- index helper: int64 vs int32 storage ----------------
__device__ __forceinline__ long long ld_idx(const void* p, long long i, int is64) {
    if (is64) return ((const long long*)p)[i];
    return (long long)((const int*)p)[i];
}

// ---------------- detect dtypes + zero degree/pool arrays (merged) -----
__global__ void detect_zero_kernel(const void* edge, const void* batch, int N) {
    int i = blockIdx.x * blockDim.x + threadIdx.x;
    if (i < N) { g_degi[i] = 0; g_cursor[i] = 0; }
    if (i < NGRAPH * HDIM) g_pool[i] = 0.0f;
    if (i < NGRAPH) g_cnt[i] = 0.0f;
    if (blockIdx.x == 0 && threadIdx.x < 64) {
        int lane = threadIdx.x & 31;
        int w    = threadIdx.x >> 5;
        const long long* p = (w == 0) ? (const long long*)edge
                                      : (const long long*)batch;
        long long v0 = p[lane * 2];
        long long v1 = p[lane * 2 + 1];
        int bad = (v0 < 0) | (v0 >= (1LL << 31)) | (v1 < 0) | (v1 >= (1LL << 31));
        unsigned m = __ballot_sync(0xFFFFFFFFu, bad);
        if (lane == 0) {
            int ok = (m == 0u);
            if (w == 0) g_edge_is64 = ok; else g_batch_is64 = ok;
        }
    }
}

__global__ void count_deg_kernel(const void* edge, int E) {
    int e = blockIdx.x * blockDim.x + threadIdx.x;
    if (e >= E) return;
    int is64 = g_edge_is64;
    int d = (int)ld_idx(edge, (long long)E + e, is64);
    atomicAdd(&g_degi[d], 1);
}

// also packs x4 = [a, pos] (fused; same launch shape)
__global__ void dinv_kernel(const float* __restrict__ an,
                            const float* __restrict__ pos, int N) {
    int i = blockIdx.x * blockDim.x + threadIdx.x;
    if (i >= N) return;
    g_deg[i] = (float)(1.0 / sqrt((double)(g_degi[i] + 1)));
    float4 x;
    x.x = an[i];
    x.y = pos[3 * i + 0];
    x.z = pos[3 * i + 1];
    x.w = pos[3 * i + 2];
    g_x4[i] = x;
}

// ---------------- exclusive prefix scan of g_degi -> g_off ----------------
__global__ void __launch_bounds__(256) scan1_kernel(int N) {
    __shared__ int sh[256];
    int t = threadIdx.x;
    int base = blockIdx.x * 1024 + t * 4;
    int v0 = (base + 0 < N) ? g_degi[base + 0] : 0;
    int v1 = (base + 1 < N) ? g_degi[base + 1] : 0;
    int v2 = (base + 2 < N) ? g_degi[base + 2] : 0;
    int v3 = (base + 3 < N) ? g_degi[base + 3] : 0;
    int sum = v0 + v1 + v2 + v3;
    sh[t] = sum;
    __syncthreads();
    for (int o = 1; o < 256; o <<= 1) {
        int x = (t >= o) ? sh[t - o] : 0;
        __syncthreads();
        sh[t] += x;
        __syncthreads();
    }
    if (t == 255) g_blocksum[blockIdx.x] = sh[255];
    int run = sh[t] - sum;
    if (base + 0 < N) { g_off[base + 0] = run; run += v0; }
    if (base + 1 < N) { g_off[base + 1] = run; run += v1; }
    if (base + 2 < N) { g_off[base + 2] = run; run += v2; }
    if (base + 3 < N) { g_off[base + 3] = run; }
}

__global__ void scan2_kernel(int nb) {
    __shared__ int sh[128];
    int t = threadIdx.x;
    int v = (t < nb) ? g_blocksum[t] : 0;
    sh[t] = v;
    __syncthreads();
    for (int o = 1; o < 128; o <<= 1) {
        int x = (t >= o) ? sh[t - o] : 0;
        __syncthreads();
        sh[t] += x;
        __syncthreads();
    }
    g_blocksum[t] = sh[t] - v;
}

__global__ void scan3_kernel(int N) {
    int i = blockIdx.x * blockDim.x + threadIdx.x;
    if (i < N) g_off[i] += g_blocksum[i >> 10];
}

// ---------------- CSR scatter ----------------
__global__ void scatter_kernel(const void* edge, int E) {
    int e = blockIdx.x * blockDim.x + threadIdx.x;
    if (e >= E) return;
    int is64 = g_edge_is64;
    int s = (int)ld_idx(edge, e, is64);
    int d = (int)ld_idx(edge, (long long)E + e, is64);
    int pos = atomicAdd(&g_cursor[d], 1);
    int2 ent;
    ent.x = s;
    ent.y = __float_as_int(g_deg[s]);
    g_csr[g_off[d] + pos] = ent;
}

// ---------------- layer-1 aggregation on RAW 4-dim features ------------
__global__ void __launch_bounds__(256) agg4_kernel(int N) {
    int d = blockIdx.x * blockDim.x + threadIdx.x;
    if (d >= N) return;
    int off = g_off[d];
    int deg = g_degi[d];
    float dn = g_deg[d];

    float4 x = g_x4[d];
    float4 acc;
    acc.x = x.x * dn; acc.y = x.y * dn; acc.z = x.z * dn; acc.w = x.w * dn;

    int end = off + deg;
    int e0 = off;
    for (; e0 + 4 <= end; e0 += 4) {
        int2 en0 = ldcs_int2(&g_csr[e0 + 0]);
        int2 en1 = ldcs_int2(&g_csr[e0 + 1]);
        int2 en2 = ldcs_int2(&g_csr[e0 + 2]);
        int2 en3 = ldcs_int2(&g_csr[e0 + 3]);
        float4 v0 = g_x4[en0.x];
        float4 v1 = g_x4[en1.x];
        float4 v2 = g_x4[en2.x];
        float4 v3 = g_x4[en3.x];
        float w0 = __int_as_float(en0.y), w1 = __int_as_float(en1.y);
        float w2 = __int_as_float(en2.y), w3 = __int_as_float(en3.y);
        acc.x += w0 * v0.x; acc.y += w0 * v0.y; acc.z += w0 * v0.z; acc.w += w0 * v0.w;
        acc.x += w1 * v1.x; acc.y += w1 * v1.y; acc.z += w1 * v1.z; acc.w += w1 * v1.w;
        acc.x += w2 * v2.x; acc.y += w2 * v2.y; acc.z += w2 * v2.z; acc.w += w2 * v2.w;
        acc.x += w3 * v3.x; acc.y += w3 * v3.y; acc.z += w3 * v3.z; acc.w += w3 * v3.w;
    }
    for (; e0 < end; e0++) {
        int2 en = ldcs_int2(&g_csr[e0]);
        float4 v = g_x4[en.x];
        float w = __int_as_float(en.y);
        acc.x += w * v.x; acc.y += w * v.y; acc.z += w * v.z; acc.w += w * v.w;
    }
    acc.x *= dn; acc.y *= dn; acc.z *= dn; acc.w *= dn;
    g_x4agg[d] = acc;
}

// ---------------- shared gather body for agg kernels -------------------
// Computes relu(dinv*(sum + self) + bias) for node d; returns float4 of
// lane's 4 columns. (identical arithmetic to R10-R14 agg)
__device__ __forceinline__ float4 agg_node_body(int d, int lane,
                                                const float* __restrict__ bias) {
    int off = g_off[d];
    int deg = g_degi[d];
    float dn = g_deg[d];

    float4 h = ((const float4*)&g_buf1[(size_t)d * HDIM])[lane];
    float4 acc;
    acc.x = h.x * dn; acc.y = h.y * dn; acc.z = h.z * dn; acc.w = h.w * dn;

    int end = off + deg;
    int e0 = off;
    for (; e0 + 8 <= end; e0 += 8) {
        int2 en0 = ldcs_int2(&g_csr[e0 + 0]);
        int2 en1 = ldcs_int2(&g_csr[e0 + 1]);
        int2 en2 = ldcs_int2(&g_csr[e0 + 2]);
        int2 en3 = ldcs_int2(&g_csr[e0 + 3]);
        int2 en4 = ldcs_int2(&g_csr[e0 + 4]);
        int2 en5 = ldcs_int2(&g_csr[e0 + 5]);
        int2 en6 = ldcs_int2(&g_csr[e0 + 6]);
        int2 en7 = ldcs_int2(&g_csr[e0 + 7]);
        float4 v0 = ((const float4*)&g_buf1[(size_t)en0.x * HDIM])[lane];
        float4 v1 = ((const float4*)&g_buf1[(size_t)en1.x * HDIM])[lane];
        float4 v2 = ((const float4*)&g_buf1[(size_t)en2.x * HDIM])[lane];
        float4 v3 = ((const float4*)&g_buf1[(size_t)en3.x * HDIM])[lane];
        float4 v4 = ((const float4*)&g_buf1[(size_t)en4.x * HDIM])[lane];
        float4 v5 = ((const float4*)&g_buf1[(size_t)en5.x * HDIM])[lane];
        float4 v6 = ((const float4*)&g_buf1[(size_t)en6.x * HDIM])[lane];
        float4 v7 = ((const float4*)&g_buf1[(size_t)en7.x * HDIM])[lane];
        float w0 = __int_as_float(en0.y), w1 = __int_as_float(en1.y);
        float w2 = __int_as_float(en2.y), w3 = __int_as_float(en3.y);
        float w4 = __int_as_float(en4.y), w5 = __int_as_float(en5.y);
        float w6 = __int_as_float(en6.y), w7 = __int_as_float(en7.y);
        acc.x += w0 * v0.x; acc.y += w0 * v0.y; acc.z += w0 * v0.z; acc.w += w0 * v0.w;
        acc.x += w1 * v1.x; acc.y += w1 * v1.y; acc.z += w1 * v1.z; acc.w += w1 * v1.w;
        acc.x += w2 * v2.x; acc.y += w2 * v2.y; acc.z += w2 * v2.z; acc.w += w2 * v2.w;
        acc.x += w3 * v3.x; acc.y += w3 * v3.y; acc.z += w3 * v3.z; acc.w += w3 * v3.w;
        acc.x += w4 * v4.x; acc.y += w4 * v4.y; acc.z += w4 * v4.z; acc.w += w4 * v4.w;
        acc.x += w5 * v5.x; acc.y += w5 * v5.y; acc.z += w5 * v5.z; acc.w += w5 * v5.w;
        acc.x += w6 * v6.x; acc.y += w6 * v6.y; acc.z += w6 * v6.z; acc.w += w6 * v6.w;
        acc.x += w7 * v7.x; acc.y += w7 * v7.y; acc.z += w7 * v7.z; acc.w += w7 * v7.w;
    }
    for (; e0 + 4 <= end; e0 += 4) {
        int2 en0 = ldcs_int2(&g_csr[e0 + 0]);
        int2 en1 = ldcs_int2(&g_csr[e0 + 1]);
        int2 en2 = ldcs_int2(&g_csr[e0 + 2]);
        int2 en3 = ldcs_int2(&g_csr[e0 + 3]);
        float4 v0 = ((const float4*)&g_buf1[(size_t)en0.x * HDIM])[lane];
        float4 v1 = ((const float4*)&g_buf1[(size_t)en1.x * HDIM])[lane];
        float4 v2 = ((const float4*)&g_buf1[(size_t)en2.x * HDIM])[lane];
        float4 v3 = ((const float4*)&g_buf1[(size_t)en3.x * HDIM])[lane];
        float w0 = __int_as_float(en0.y), w1 = __int_as_float(en1.y);
        float w2 = __int_as_float(en2.y), w3 = __int_as_float(en3.y);
        acc.x += w0 * v0.x; acc.y += w0 * v0.y; acc.z += w0 * v0.z; acc.w += w0 * v0.w;
        acc.x += w1 * v1.x; acc.y += w1 * v1.y; acc.z += w1 * v1.z; acc.w += w1 * v1.w;
        acc.x += w2 * v2.x; acc.y += w2 * v2.y; acc.z += w2 * v2.z; acc.w += w2 * v2.w;
        acc.x += w3 * v3.x; acc.y += w3 * v3.y; acc.z += w3 * v3.z; acc.w += w3 * v3.w;
    }
    for (; e0 < end; e0++) {
        int2 en = ldcs_int2(&g_csr[e0]);
        float4 v = ((const float4*)&g_buf1[(size_t)en.x * HDIM])[lane];
        float w = __int_as_float(en.y);
        acc.x += w * v.x; acc.y += w * v.y; acc.z += w * v.z; acc.w += w * v.w;
    }

    float4 b = ((const float4*)bias)[lane];
    float4 r;
    r.x = fmaxf(acc.x * dn + b.x, 0.0f);
    r.y = fmaxf(acc.y * dn + b.y, 0.0f);
    r.z = fmaxf(acc.z * dn + b.z, 0.0f);
    r.w = fmaxf(acc.w * dn + b.w, 0.0f);
    return r;
}

// ---------------- layer-2 aggregation: writes buf0 for gemm2 ----------
__global__ void __launch_bounds__(256) agg_kernel(const float* __restrict__ bias, int N) {
    int warp = (blockIdx.x * 256 + threadIdx.x) >> 5;
    int lane = threadIdx.x & 31;
    if (warp >= N) return;
    float4 r = agg_node_body(warp, lane, bias);
    stcs_float4(&((float4*)&g_buf0[(size_t)warp * HDIM])[lane], r);
}

// ---------------- layer-3 aggregation FUSED with global mean pooling ---
// Each block handles 8 consecutive nodes (batch sorted). Rows staged in
// shared, column-wise run-detected reduction, one red.global per run.
// Eliminates the 51MB buf0 write + 51MB pool_acc read + one launch.
__global__ void __launch_bounds__(256) agg_pool_kernel(const float* __restrict__ bias,
                                                       const void* batch, int N) {
    __shared__ float s_rows[8][HDIM];
    __shared__ int   s_g[8];
    int warp = threadIdx.x >> 5;
    int lane = threadIdx.x & 31;
    int d = blockIdx.x * 8 + warp;

    float4 r = make_float4(0.f, 0.f, 0.f, 0.f);
    int g = -1;
    if (d < N) {
        r = agg_node_body(d, lane, bias);
        g = (int)ld_idx(batch, d, g_batch_is64);
    }
    ((float4*)s_rows[warp])[lane] = r;
    if (lane == 0) s_g[warp] = g;
    __syncthreads();

    int c = threadIdx.x;
    if (c < HDIM) {
        float acc = 0.0f;
        int cur = -1;
        #pragma unroll
        for (int w = 0; w < 8; w++) {
            int gw = s_g[w];
            if (gw < 0) continue;           // invalid tail nodes
            if (gw != cur) {
                if (cur >= 0) red_add_f32(&g_pool[cur * HDIM + c], acc);
                cur = gw; acc = 0.0f;
            }
            acc += s_rows[w][c];
        }
        if (cur >= 0) red_add_f32(&g_pool[cur * HDIM + c], acc);
    }
    if (threadIdx.x == 255) {               // counts: one thread per block
        float cnt = 0.0f;
        int cur = -1;
        #pragma unroll
        for (int w = 0; w < 8; w++) {
            int gw = s_g[w];
            if (gw < 0) continue;
            if (gw != cur) {
                if (cur >= 0) red_add_f32(&g_cnt[cur], cnt);
                cur = gw; cnt = 0.0f;
            }
            cnt += 1.0f;
        }
        if (cur >= 0) red_add_f32(&g_cnt[cur], cnt);
    }
}

// ---------------- TF32 tensor-core GEMM core ---------------------------
__device__ __forceinline__ void gemm_mma_body(
    float (*Xs)[132], float (*Ws)[136],
    const float* __restrict__ W, int n0, int N, int tid)
{
    int warp = tid >> 5;
    int lane = tid & 31;
    float acc[16][4];
    #pragma unroll
    for (int nt = 0; nt < 16; nt++) {
        acc[nt][0] = 0.f; acc[nt][1] = 0.f; acc[nt][2] = 0.f; acc[nt][3] = 0.f;
    }

    int r0 = warp * 16;
    int qr = lane >> 2;       // 0..7
    int qc = lane & 3;        // 0..3

    for (int ks = 0; ks < 16; ks++) {
        __syncthreads();
        #pragma unroll
        for (int i = 0; i < 8; i++)
            Ws[i][tid] = to_tf32f(W[(ks * 8 + i) * HDIM + tid]);
        __syncthreads();

        int acol = ks * 8 + qc;
        unsigned int a0 = __float_as_uint(Xs[r0 + qr][acol]);
        unsigned int a1 = __float_as_uint(Xs[r0 + qr + 8][acol]);
        unsigned int a2 = __float_as_uint(Xs[r0 + qr][acol + 4]);
        unsigned int a3 = __float_as_uint(Xs[r0 + qr + 8][acol + 4]);

        #pragma unroll
        for (int nt = 0; nt < 16; nt++) {
            unsigned int b0 = __float_as_uint(Ws[qc][nt * 8 + qr]);
            unsigned int b1 = __float_as_uint(Ws[qc + 4][nt * 8 + qr]);
            asm volatile(
                "mma.sync.aligned.m16n8k8.row.col.f32.tf32.tf32.f32 "
                "{%0,%1,%2,%3}, {%4,%5,%6,%7}, {%8,%9}, {%0,%1,%2,%3};"
                : "+f"(acc[nt][0]), "+f"(acc[nt][1]),
                  "+f"(acc[nt][2]), "+f"(acc[nt][3])
                : "r"(a0), "r"(a1), "r"(a2), "r"(a3), "r"(b0), "r"(b1));
        }
    }

    int rowA = n0 + r0 + qr;
    int rowB = rowA + 8;
    #pragma unroll
    for (int nt = 0; nt < 16; nt++) {
        int col = nt * 8 + 2 * qc;
        if (rowA < N) {
            float2 v = make_float2(acc[nt][0], acc[nt][1]);
            *reinterpret_cast<float2*>(&g_buf1[(size_t)rowA * HDIM + col]) = v;
        }
        if (rowB < N) {
            float2 v = make_float2(acc[nt][2], acc[nt][3]);
            *reinterpret_cast<float2*>(&g_buf1[(size_t)rowB * HDIM + col]) = v;
        }
    }
}

#define GROWS 64

// layer-2 gemm: stages X by computing layer-1 transform on the fly
__global__ void __launch_bounds__(128) gemm1_kernel(const float* __restrict__ W0,
                                                    const float* __restrict__ b0,
                                                    const float* __restrict__ W1, int N) {
    __shared__ float Xs[GROWS][132];   // 33 KB
    __shared__ float Ws[8][136];       // 4.25 KB
    int n0  = blockIdx.x * GROWS;
    int tid = threadIdx.x;

    float w0 = to_tf32f(W0[tid]);
    float w1 = to_tf32f(W0[HDIM + tid]);
    float w2 = to_tf32f(W0[2 * HDIM + tid]);
    float w3 = to_tf32f(W0[3 * HDIM + tid]);
    float bb = b0[tid];

    for (int r = 0; r < GROWS; r++) {
        int n = n0 + r;
        float4 x = (n < N) ? g_x4agg[n] : make_float4(0.f, 0.f, 0.f, 0.f);
        float h = to_tf32f(x.x) * w0;
        h += to_tf32f(x.y) * w1;
        h += to_tf32f(x.z) * w2;
        h += to_tf32f(x.w) * w3;
        h += bb;
        Xs[r][tid] = to_tf32f(h > 0.0f ? h : 0.0f);
    }
    gemm_mma_body(Xs, Ws, W1, n0, N, tid);
}

// layer-3 gemm: stages X from buf0 (layer-2 agg output)
__global__ void __launch_bounds__(128) gemm2_kernel(const float* __restrict__ W, int N) {
    __shared__ float Xs[GROWS][132];
    __shared__ float Ws[8][136];
    int n0  = blockIdx.x * GROWS;
    int tid = threadIdx.x;

    for (int r = 0; r < GROWS; r++) {
        int n = n0 + r;
        float v = (n < N) ? g_buf0[(size_t)n * HDIM + tid] : 0.0f;
        Xs[r][tid] = to_tf32f(v);
    }
    gemm_mma_body(Xs, Ws, W, n0, N, tid);
}

// ---------------- head: mean, linear(128->8) tf32-emulated, ------------
// ---------------- softmax in double ------------------------------------
__global__ void final_kernel(const float* __restrict__ linW,
                             const float* __restrict__ linb,
                             float* __restrict__ out) {
    int t = threadIdx.x;             // 512 = 64 graphs * 8 experts
    int g = t >> 3, e = t & 7;
    float c = fmaxf(g_cnt[g], 1.0f);
    float acc = 0.0f;
    #pragma unroll 8
    for (int k = 0; k < HDIM; k++) {
        float p = to_tf32f(g_pool[g * HDIM + k] / c);
        float w = to_tf32f(linW[k * 8 + e]);
        acc += p * w;
    }
    double logit = (double)acc + (double)linb[e];
    double m = logit;
    for (int o = 4; o >= 1; o >>= 1) {
        double other = __shfl_xor_sync(0xFFFFFFFFu, m, o);
        m = fmax(m, other);
    }
    double ex = exp(logit - m);
    double s = ex;
    for (int o = 4; o >= 1; o >>= 1)
        s += __shfl_xor_sync(0xFFFFFFFFu, s, o);
    out[t] = (float)(ex / s);
}

// ---------------- launch ----------------
extern "C" void kernel_launch(void* const* d_in, const int* in_sizes, int n_in,
                              void* d_out, int out_size) {
    const float* an   = (const float*)d_in[0];
    const float* pos  = (const float*)d_in[1];
    const float* W0   = (const float*)d_in[2];
    const float* b0   = (const float*)d_in[3];
    const float* W1   = (const float*)d_in[4];
    const float* b1   = (const float*)d_in[5];
    const float* W2   = (const float*)d_in[6];
    const float* b2   = (const float*)d_in[7];
    const float* linW = (const float*)d_in[8];
    const float* linb = (const float*)d_in[9];
    const void*  edge = d_in[10];
    const void*  batch= d_in[11];
    int N = in_sizes[0];
    int E = in_sizes[10] / 2;
    float* out = (float*)d_out;

    // prologue: zero + detect, degrees, norms, CSR
    detect_zero_kernel<<<(N + 255) / 256, 256>>>(edge, batch, N);
    count_deg_kernel<<<(E + 255) / 256, 256>>>(edge, E);
    dinv_kernel<<<(N + 255) / 256, 256>>>(an, pos, N);
    int nb = (N + 1023) / 1024;
    scan1_kernel<<<nb, 256>>>(N);
    scan2_kernel<<<1, 128>>>(nb);
    scan3_kernel<<<(N + 255) / 256, 256>>>(N);
    scatter_kernel<<<(E + 255) / 256, 256>>>(edge, E);

    int agg_grid = (N + 7) / 8;
    // layer 1: aggregate raw 4-dim features (transform fused into gemm1)
    agg4_kernel<<<(N + 255) / 256, 256>>>(N);
    // layer 2 (stages layer-1 transform on the fly)
    gemm1_kernel<<<(N + GROWS - 1) / GROWS, 128>>>(W0, b0, W1, N);
    agg_kernel<<<agg_grid, 256>>>(b1, N);
    // layer 3 (aggregation fused with pooling)
    gemm2_kernel<<<(N + GROWS - 1) / GROWS, 128>>>(W2, N);
    agg_pool_kernel<<<agg_grid, 256>>>(b2, batch, N);
    // head
    final_kernel<<<1, 512>>>(linW, linb, out);
}